// round 8
// baseline (speedup 1.0000x reference)
#include <cuda_runtime.h>

#define BB 8
#define NN 10000
#define EE 160000
#define BN 80000          // B*N nodes
#define BE 1280000        // B*E edges
#define NBLK 313          // ceil(BN/256)

// ---- scratch: __device__ globals, referenced only from device code ----
__device__ float g_tmp[BN * 64];     // transformed features (h @ W^T + b)
__device__ float g_agg[BN * 64];     // aggregated features
__device__ int   g_deg[BN];
__device__ int   g_cursor[BN];
__device__ int   g_rowstart[BN + 1];
__device__ int   g_blocksum[NBLK];
__device__ int   g_blockoff[NBLK];
__device__ float g_dinv[BN];
__device__ int   g_ecol[BE];         // CSR column ids
__device__ float g_enrm[BE];         // CSR per-edge norm

// ---------------------------------------------------------
__global__ void init_kernel() {
    int i = blockIdx.x * blockDim.x + threadIdx.x;
    if (i < BN) { g_deg[i] = 0; g_cursor[i] = 0; }
}

// edge_index is int32 on device (JAX default config downcasts int64 -> int32).
// Layout [B, E, 2]: edge g has (row, col) at int offsets {2g, 2g+1} -> one int2.
__global__ void count_kernel(const int2* __restrict__ ei) {
    int g = blockIdx.x * blockDim.x + threadIdx.x;
    if (g >= BE) return;
    int2 p = ei[g];
    int b = g / EE;
    atomicAdd(&g_deg[p.x + b * NN], 1);
}

// two-level exclusive scan of g_deg -> g_rowstart
__global__ void scanA_kernel() {            // block-local scan + block totals
    __shared__ int s[256];
    int tid = threadIdx.x;
    int i = blockIdx.x * 256 + tid;
    int v = (i < BN) ? g_deg[i] : 0;
    s[tid] = v;
    __syncthreads();
    for (int off = 1; off < 256; off <<= 1) {
        int t = (tid >= off) ? s[tid - off] : 0;
        __syncthreads();
        s[tid] += t;
        __syncthreads();
    }
    if (i < BN) g_rowstart[i] = s[tid] - v;       // block-local exclusive
    if (tid == 255) g_blocksum[blockIdx.x] = s[255];
}

__global__ void scanB_kernel() {            // serial scan of 313 block totals
    if (threadIdx.x == 0 && blockIdx.x == 0) {
        int run = 0;
        for (int b = 0; b < NBLK; b++) {
            g_blockoff[b] = run;
            run += g_blocksum[b];
        }
        g_rowstart[BN] = run;
    }
}

__global__ void scanC_kernel() {            // add block offsets + compute dinv
    int i = blockIdx.x * 256 + threadIdx.x;
    if (i < BN) {
        g_rowstart[i] += g_blockoff[blockIdx.x];
        int d = g_deg[i];
        g_dinv[i] = (d > 0) ? rsqrtf((float)d) : 0.0f;
    }
}

__global__ void bin_kernel(const int2* __restrict__ ei) {
    int g = blockIdx.x * blockDim.x + threadIdx.x;
    if (g >= BE) return;
    int2 p = ei[g];
    int b = g / EE;
    int row = p.x + b * NN;
    int col = p.y + b * NN;
    float nrm = g_dinv[row] * g_dinv[col];
    int pos = g_rowstart[row] + atomicAdd(&g_cursor[row], 1);
    g_ecol[pos] = col;
    g_enrm[pos] = nrm;
}

// ---------------------------------------------------------
// g_tmp[i][j] = sum_k src[i][k] * W[j][k] + bias[j]
// src = xin when from_x != 0, else g_agg. 128 threads: 64x64 tile, 4x8 micro.
__global__ void __launch_bounds__(128) gemm_kernel(
        const float* __restrict__ xin, const float* __restrict__ W,
        const float* __restrict__ bias, int from_x) {
    __shared__ float s_in[64][65];
    __shared__ float s_wt[64][65];   // s_wt[k][j] = W[j][k]
    __shared__ float s_b[64];

    int tid = threadIdx.x;
    size_t row0 = (size_t)blockIdx.x * 64;

    for (int i = tid; i < 64 * 64; i += 128) {
        int j = i >> 6, k = i & 63;
        s_wt[k][j] = W[i];
    }
    if (tid < 64) s_b[tid] = bias[tid];

    const float* src = from_x ? xin : (const float*)g_agg;
    for (int f = tid; f < 64 * 64; f += 128) {
        int r = f >> 6, c = f & 63;
        s_in[r][c] = src[row0 * 64 + f];
    }
    __syncthreads();

    int cg = tid & 7;    // cols cg*8 .. cg*8+7
    int rg = tid >> 3;   // rows rg*4 .. rg*4+3

    float acc[4][8];
    #pragma unroll
    for (int c = 0; c < 8; c++) {
        float bv = s_b[cg * 8 + c];
        acc[0][c] = bv; acc[1][c] = bv; acc[2][c] = bv; acc[3][c] = bv;
    }

    #pragma unroll 4
    for (int k = 0; k < 64; k++) {
        float w[8];
        #pragma unroll
        for (int c = 0; c < 8; c++) w[c] = s_wt[k][cg * 8 + c];
        #pragma unroll
        for (int r = 0; r < 4; r++) {
            float a = s_in[rg * 4 + r][k];
            #pragma unroll
            for (int c = 0; c < 8; c++) acc[r][c] += a * w[c];
        }
    }

    #pragma unroll
    for (int r = 0; r < 4; r++) {
        float* o = g_tmp + (row0 + rg * 4 + r) * 64 + cg * 8;
        #pragma unroll
        for (int c = 0; c < 8; c++) o[c] = acc[r][c];
    }
}

// ---------------------------------------------------------
// one warp per row; lane handles features lane and lane+32 (coalesced 128B x2)
__global__ void __launch_bounds__(256) agg_kernel(
        float* __restrict__ outp, int relu, int to_out) {
    int warp = (blockIdx.x * blockDim.x + threadIdx.x) >> 5;
    int lane = threadIdx.x & 31;
    if (warp >= BN) return;

    int s = g_rowstart[warp];
    int e = g_rowstart[warp + 1];

    float a0 = 0.0f, a1 = 0.0f;
    for (int i = s; i < e; i++) {
        int col  = g_ecol[i];           // broadcast
        float nm = g_enrm[i];           // broadcast
        const float* hp = g_tmp + (size_t)col * 64;
        a0 += nm * hp[lane];
        a1 += nm * hp[lane + 32];
    }
    if (relu) { a0 = fmaxf(a0, 0.0f); a1 = fmaxf(a1, 0.0f); }
    float* dst = to_out ? outp : (float*)g_agg;
    dst[(size_t)warp * 64 + lane]      = a0;
    dst[(size_t)warp * 64 + lane + 32] = a1;
}

// ---------------------------------------------------------
extern "C" void kernel_launch(void* const* d_in, const int* in_sizes, int n_in,
                              void* d_out, int out_size) {
    const float* x  = (const float*)d_in[0];
    const int2*  ei = (const int2*)d_in[1];
    const float* W1 = (const float*)d_in[2];
    const float* b1 = (const float*)d_in[3];
    const float* W2 = (const float*)d_in[4];
    const float* b2 = (const float*)d_in[5];
    const float* W3 = (const float*)d_in[6];
    const float* b3 = (const float*)d_in[7];
    float* out = (float*)d_out;

    const int TB = 256;
    int edgeBlocks = (BE + TB - 1) / TB;       // 5000
    int gemmBlocks = BN / 64;                  // 1250
    int aggBlocks  = (BN * 32) / TB;           // 10000

    // CSR build (identical inputs each call -> deterministic)
    init_kernel <<<NBLK, TB>>>();
    count_kernel<<<edgeBlocks, TB>>>(ei);
    scanA_kernel<<<NBLK, TB>>>();
    scanB_kernel<<<1, 32>>>();
    scanC_kernel<<<NBLK, TB>>>();
    bin_kernel  <<<edgeBlocks, TB>>>(ei);

    // layer 1
    gemm_kernel<<<gemmBlocks, 128>>>(x, W1, b1, 1);
    agg_kernel <<<aggBlocks, TB>>>(out, 1, 0);
    // layer 2
    gemm_kernel<<<gemmBlocks, 128>>>(x, W2, b2, 0);
    agg_kernel <<<aggBlocks, TB>>>(out, 1, 0);
    // layer 3
    gemm_kernel<<<gemmBlocks, 128>>>(x, W3, b3, 0);
    agg_kernel <<<aggBlocks, TB>>>(out, 0, 1);
}

// round 9
// speedup vs baseline: 1.1827x; 1.1827x over previous
#include <cuda_runtime.h>

#define NN 10000
#define EE 160000
#define BN 80000          // B*N nodes
#define BE 1280000        // B*E edges
#define NBLK 313          // ceil(BN/256)

// ---- scratch: __device__ globals, referenced only from device code ----
__device__ float g_tmp[BN * 64];     // transformed features (h @ W^T + b)
__device__ float g_agg[BN * 64];     // aggregated features
__device__ int   g_deg[BN];
__device__ int   g_cursor[BN];
__device__ int   g_rowstart[BN];
__device__ float g_dinv[BN];
__device__ int   g_total;            // segment allocator
__device__ int   g_ecol[BE];         // CSR column ids
__device__ float g_enrm[BE];         // CSR per-edge norm

// ---------------------------------------------------------
__global__ void init_kernel() {
    int i = blockIdx.x * blockDim.x + threadIdx.x;
    if (i < BN) g_deg[i] = 0;
    if (i == 0) g_total = 0;
}

// edge_index is int32 on device; layout [B,E,2] -> one int2 per edge.
__global__ void count_kernel(const int2* __restrict__ ei) {
    int g = blockIdx.x * blockDim.x + threadIdx.x;
    if (g >= BE) return;
    int2 p = ei[g];
    int b = g / EE;
    atomicAdd(&g_deg[p.x + b * NN], 1);
}

// Fused segment allocation: block-local scan + ONE atomicAdd per block.
// Segment order across blocks is arbitrary — irrelevant for correctness.
// Also computes dinv and zeroes the fill cursors.
__global__ void alloc_kernel() {
    __shared__ int s[256];
    __shared__ int base;
    int tid = threadIdx.x;
    int i = blockIdx.x * 256 + tid;
    int v = (i < BN) ? g_deg[i] : 0;
    s[tid] = v;
    __syncthreads();
    #pragma unroll
    for (int off = 1; off < 256; off <<= 1) {
        int t = (tid >= off) ? s[tid - off] : 0;
        __syncthreads();
        s[tid] += t;
        __syncthreads();
    }
    if (tid == 255) base = atomicAdd(&g_total, s[255]);
    __syncthreads();
    if (i < BN) {
        g_rowstart[i] = base + s[tid] - v;       // exclusive within block + base
        g_cursor[i] = 0;
        g_dinv[i] = (v > 0) ? rsqrtf((float)v) : 0.0f;
    }
}

__global__ void bin_kernel(const int2* __restrict__ ei) {
    int g = blockIdx.x * blockDim.x + threadIdx.x;
    if (g >= BE) return;
    int2 p = ei[g];
    int b = g / EE;
    int row = p.x + b * NN;
    int col = p.y + b * NN;
    float nrm = g_dinv[row] * g_dinv[col];
    int pos = g_rowstart[row] + atomicAdd(&g_cursor[row], 1);
    g_ecol[pos] = col;
    g_enrm[pos] = nrm;
}

// ---------------------------------------------------------
// g_tmp[i][j] = sum_k src[i][k] * W[j][k] + bias[j]
// 128 threads: 64x64 tile, per-thread 4 rows x 8 cols.
__global__ void __launch_bounds__(128) gemm_kernel(
        const float* __restrict__ xin, const float* __restrict__ W,
        const float* __restrict__ bias, int from_x) {
    __shared__ float s_in[64][66];   // row stride 66: float2-aligned, banks(264%32=8)
    __shared__ float s_wt[64][66];   // s_wt[k][j] = W[j][k]
    __shared__ float s_b[64];

    int tid = threadIdx.x;
    size_t row0 = (size_t)blockIdx.x * 64;

    // stage W transposed: float4 gmem loads, scalar smem scatter
    {
        const float4* W4 = (const float4*)W;
        #pragma unroll
        for (int it = 0; it < 8; it++) {
            int q = tid + it * 128;          // q over [64 j][16 kq]
            int j = q >> 4, kq = (q & 15) << 2;
            float4 w = W4[q];
            s_wt[kq + 0][j] = w.x;
            s_wt[kq + 1][j] = w.y;
            s_wt[kq + 2][j] = w.z;
            s_wt[kq + 3][j] = w.w;
        }
    }
    if (tid < 64) s_b[tid] = bias[tid];

    // stage input tile: float2 path (row stride 66 keeps 8B alignment)
    {
        const float* src = from_x ? xin : (const float*)g_agg;
        const float2* in2 = (const float2*)(src + row0 * 64);
        #pragma unroll
        for (int it = 0; it < 16; it++) {
            int f = tid + it * 128;          // f over [64 r][32 c2]
            int r = f >> 5, c2 = f & 31;
            *(float2*)&s_in[r][c2 * 2] = in2[f];
        }
    }
    __syncthreads();

    int cg = tid & 7;    // cols cg*8 .. cg*8+7
    int rg = tid >> 3;   // rows rg*4 .. rg*4+3

    float acc[4][8];
    #pragma unroll
    for (int c = 0; c < 8; c++) {
        float bv = s_b[cg * 8 + c];
        acc[0][c] = bv; acc[1][c] = bv; acc[2][c] = bv; acc[3][c] = bv;
    }

    #pragma unroll 4
    for (int k = 0; k < 64; k++) {
        float2 w01 = *(const float2*)&s_wt[k][cg * 8 + 0];
        float2 w23 = *(const float2*)&s_wt[k][cg * 8 + 2];
        float2 w45 = *(const float2*)&s_wt[k][cg * 8 + 4];
        float2 w67 = *(const float2*)&s_wt[k][cg * 8 + 6];
        #pragma unroll
        for (int r = 0; r < 4; r++) {
            float a = s_in[rg * 4 + r][k];
            acc[r][0] += a * w01.x; acc[r][1] += a * w01.y;
            acc[r][2] += a * w23.x; acc[r][3] += a * w23.y;
            acc[r][4] += a * w45.x; acc[r][5] += a * w45.y;
            acc[r][6] += a * w67.x; acc[r][7] += a * w67.y;
        }
    }

    #pragma unroll
    for (int r = 0; r < 4; r++) {
        float4* o = (float4*)(g_tmp + (row0 + rg * 4 + r) * 64 + cg * 8);
        o[0] = make_float4(acc[r][0], acc[r][1], acc[r][2], acc[r][3]);
        o[1] = make_float4(acc[r][4], acc[r][5], acc[r][6], acc[r][7]);
    }
}

// ---------------------------------------------------------
// one warp per row; lane handles one float2 (coalesced 256B per edge)
__global__ void __launch_bounds__(256) agg_kernel(
        float* __restrict__ outp, int relu, int to_out) {
    int warp = (blockIdx.x * blockDim.x + threadIdx.x) >> 5;
    int lane = threadIdx.x & 31;
    if (warp >= BN) return;

    int s = g_rowstart[warp];
    int e = s + g_deg[warp];

    float ax = 0.0f, ay = 0.0f;
    for (int i = s; i < e; i++) {
        int col  = g_ecol[i];           // broadcast
        float nm = g_enrm[i];           // broadcast
        float2 v = *(const float2*)(g_tmp + (size_t)col * 64 + lane * 2);
        ax += nm * v.x;
        ay += nm * v.y;
    }
    if (relu) { ax = fmaxf(ax, 0.0f); ay = fmaxf(ay, 0.0f); }
    float* dst = to_out ? outp : (float*)g_agg;
    *(float2*)(dst + (size_t)warp * 64 + lane * 2) = make_float2(ax, ay);
}

// ---------------------------------------------------------
extern "C" void kernel_launch(void* const* d_in, const int* in_sizes, int n_in,
                              void* d_out, int out_size) {
    const float* x  = (const float*)d_in[0];
    const int2*  ei = (const int2*)d_in[1];
    const float* W1 = (const float*)d_in[2];
    const float* b1 = (const float*)d_in[3];
    const float* W2 = (const float*)d_in[4];
    const float* b2 = (const float*)d_in[5];
    const float* W3 = (const float*)d_in[6];
    const float* b3 = (const float*)d_in[7];
    float* out = (float*)d_out;

    const int TB = 256;
    int edgeBlocks = (BE + TB - 1) / TB;       // 5000
    int gemmBlocks = BN / 64;                  // 1250
    int aggBlocks  = (BN * 32) / TB;           // 10000

    // CSR build: 4 launches (no global scan — block-atomic segment allocation)
    init_kernel <<<NBLK, TB>>>();
    count_kernel<<<edgeBlocks, TB>>>(ei);
    alloc_kernel<<<NBLK, TB>>>();
    bin_kernel  <<<edgeBlocks, TB>>>(ei);

    // layer 1
    gemm_kernel<<<gemmBlocks, 128>>>(x, W1, b1, 1);
    agg_kernel <<<aggBlocks, TB>>>(out, 1, 0);
    // layer 2
    gemm_kernel<<<gemmBlocks, 128>>>(x, W2, b2, 0);
    agg_kernel <<<aggBlocks, TB>>>(out, 1, 0);
    // layer 3
    gemm_kernel<<<gemmBlocks, 128>>>(x, W3, b3, 0);
    agg_kernel <<<aggBlocks, TB>>>(out, 0, 1);
}